// round 8
// baseline (speedup 1.0000x reference)
#include <cuda_runtime.h>
#include <cstdint>

#define V_     10000
#define VPAD   10240
#define E_     128
#define NTOK   2048
#define NR     8
#define NVB    79            // v-blocks of 128 in k_base

#define KSPLIT 16
#define KQ     640           // 16*640 = 10240 = VPAD exactly

// ---------------- scratch (device globals; no allocations) ----------------
__device__ float    g_base[(size_t)NTOK * VPAD];     // q = exp(base)-1 (pad cols = 0)
__device__ uint32_t g_cls4[(size_t)NTOK * (VPAD/8)]; // 4-bit classes, 8 per word; pad = 0
__device__ float    g_colsum[E_];
__device__ float    g_part[40 * E_];
__device__ float    g_sp2[(size_t)NVB * 17 * NTOK];  // per (vblk, field, token) partials
__device__ float    g_stats[NTOK * 12];              // K1[8], beta
__device__ float    g_psum[KSPLIT][(size_t)NTOK * E_];

__device__ __forceinline__ void fma2(unsigned long long& acc,
                                     unsigned long long a, unsigned long long b) {
    asm("fma.rn.f32x2 %0, %1, %2, %0;" : "+l"(acc) : "l"(a), "l"(b));
}
__device__ __forceinline__ uint32_t s2u(const void* p) {
    return (uint32_t)__cvta_generic_to_shared(p);
}
#define CP_ASYNC16(dst, src) \
    asm volatile("cp.async.cg.shared.global [%0], [%1], 16;\n" :: "r"(dst), "l"(src))
#define CP_COMMIT() asm volatile("cp.async.commit_group;\n" ::: "memory")
#define CP_WAIT0()  asm volatile("cp.async.wait_group 0;\n" ::: "memory")

// ---------------- column sums of W (deterministic 2-stage) ----------------
__global__ void k_colsum1(const float* __restrict__ W) {
    int b = blockIdx.x, col = threadIdx.x;
    float s = 0.f;
    int v0 = b * 250;
    for (int v = v0; v < v0 + 250; v++) s += W[v * E_ + col];
    g_part[b * E_ + col] = s;
}
__global__ void k_colsum2() {
    int col = threadIdx.x;
    float s = 0.f;
    for (int b = 0; b < 40; b++) s += g_part[b * E_ + col];
    g_colsum[col] = s;
}

// ---------------- base GEMM (f32x2, 8x8 tile, double-buffered) + classify + fused stats ----------------
#define BT 64
#define BV 128
#define KCB 16

// dynamic smem layout (bytes)
#define XBUF_B   (KCB * 132 * 4)           // 8448
#define WBUF_B   (KCB * 132 * 4)           // 8448
#define OFF_XS2  0
#define OFF_WS   (2 * XBUF_B)              // 16896
#define OFF_REL  (OFF_WS + 2 * WBUF_B)     // 33792
#define OFF_EDGE (OFF_REL + 32768)         // 66560
#define OFF_SSM  (OFF_EDGE + 32768)        // 99328
#define SMEM_KB  (OFF_SSM + 256)           // 99584

__global__ __launch_bounds__(128) void k_base(
    const int*   __restrict__ src,
    const float* __restrict__ X,
    const float* __restrict__ W,
    const float* __restrict__ edge,
    const int*   __restrict__ rel)
{
    extern __shared__ char smraw[];
    float (*Xs2)[KCB][132] = (float(*)[KCB][132])(smraw + OFF_XS2);
    float (*Ws)[KCB][132]  = (float(*)[KCB][132])(smraw + OFF_WS);
    int*    rel_s  = (int*)  (smraw + OFF_REL);    // [64 tok][128 v]
    float*  edge_s = (float*)(smraw + OFF_EDGE);   // [64 tok][128 v]
    int*    ssm    = (int*)  (smraw + OFF_SSM);

    int tid  = threadIdx.x;
    int vb   = blockIdx.x;
    int vblk = vb * BV;
    int tblk = blockIdx.y * BT;
    if (tid < BT) ssm[tid] = src[tblk + tid];
    __syncthreads();

    // prefetch rel/edge tiles (64 tok x 128 v) via cp.async — hidden under GEMM
    uint32_t rel_su  = s2u(rel_s);
    uint32_t edge_su = s2u(edge_s);
#pragma unroll
    for (int j = 0; j < 16; j++) {
        int chunk = tid + 128 * j;          // 0..2047, 16B chunks
        int tok = chunk >> 5;
        int vloc = (chunk & 31) * 4;
        int v = vblk + vloc;
        if (v < V_) {
            long s = ssm[tok];
            CP_ASYNC16(rel_su  + chunk * 16, rel  + s * (long)V_ + v);
            CP_ASYNC16(edge_su + chunk * 16, edge + s * (long)V_ + v);
        }
    }
    CP_COMMIT();

    unsigned long long acc[8][4];
#pragma unroll
    for (int i = 0; i < 8; i++)
#pragma unroll
        for (int j = 0; j < 4; j++) acc[i][j] = 0ull;

    int tx = tid & 15;     // col group: 8*tx..8*tx+7
    int ty = tid >> 4;     // token group: 8*ty..8*ty+7
    int xtok = tid & 63, xkq = tid >> 6;
    int gvW  = vblk + tid;

    float4 xst[2], wst[4];
    auto stage = [&](int kc) {
#pragma unroll
        for (int j = 0; j < 2; j++) {
            int k4 = 4 * (xkq + 2 * j);
            xst[j] = *(const float4*)&X[(size_t)(tblk + xtok) * E_ + kc + k4];
        }
#pragma unroll
        for (int j = 0; j < 4; j++) {
            wst[j] = (gvW < V_) ? *(const float4*)&W[(size_t)gvW * E_ + kc + 4 * j]
                                : make_float4(0.f, 0.f, 0.f, 0.f);
        }
    };
    auto commit = [&](int buf) {
#pragma unroll
        for (int j = 0; j < 2; j++) {
            int k4 = 4 * (xkq + 2 * j);
            *(float2*)&Xs2[buf][k4 + 0][2 * xtok] = make_float2(xst[j].x, xst[j].x);
            *(float2*)&Xs2[buf][k4 + 1][2 * xtok] = make_float2(xst[j].y, xst[j].y);
            *(float2*)&Xs2[buf][k4 + 2][2 * xtok] = make_float2(xst[j].z, xst[j].z);
            *(float2*)&Xs2[buf][k4 + 3][2 * xtok] = make_float2(xst[j].w, xst[j].w);
        }
#pragma unroll
        for (int j = 0; j < 4; j++) {
            int k4 = 4 * j;
            Ws[buf][k4 + 0][tid] = wst[j].x;
            Ws[buf][k4 + 1][tid] = wst[j].y;
            Ws[buf][k4 + 2][tid] = wst[j].z;
            Ws[buf][k4 + 3][tid] = wst[j].w;
        }
    };

    stage(0);
    commit(0);
    int buf = 0;
#define NCHB (E_ / KCB)   // 8
    for (int ch = 0; ch < NCHB; ch++) {
        __syncthreads();
        if (ch + 1 < NCHB) stage((ch + 1) * KCB);
#pragma unroll
        for (int kk = 0; kk < KCB; kk++) {
            ulonglong2 w01 = *(const ulonglong2*)&Ws[buf][kk][8 * tx];
            ulonglong2 w23 = *(const ulonglong2*)&Ws[buf][kk][8 * tx + 4];
            ulonglong2 a01 = *(const ulonglong2*)&Xs2[buf][kk][16 * ty];
            ulonglong2 a23 = *(const ulonglong2*)&Xs2[buf][kk][16 * ty + 4];
            ulonglong2 a45 = *(const ulonglong2*)&Xs2[buf][kk][16 * ty + 8];
            ulonglong2 a67 = *(const ulonglong2*)&Xs2[buf][kk][16 * ty + 12];
            unsigned long long a[8] = {a01.x, a01.y, a23.x, a23.y,
                                       a45.x, a45.y, a67.x, a67.y};
            unsigned long long w[4] = {w01.x, w01.y, w23.x, w23.y};
#pragma unroll
            for (int i = 0; i < 8; i++)
#pragma unroll
                for (int j = 0; j < 4; j++)
                    fma2(acc[i][j], a[i], w[j]);
        }
        if (ch + 1 < NCHB) commit(buf ^ 1);
        buf ^= 1;
    }

    CP_WAIT0();
    __syncthreads();

    // ---- epilogue: store q, pack classes, fused per-token stats ----
    int v0 = vblk + 8 * tx;
#pragma unroll
    for (int i = 0; i < 8; i++) {
        int tl = 8 * ty + i;
        int t  = tblk + tl;
        float bs[8];
        *(float2*)&bs[0] = *(float2*)&acc[i][0];
        *(float2*)&bs[2] = *(float2*)&acc[i][1];
        *(float2*)&bs[4] = *(float2*)&acc[i][2];
        *(float2*)&bs[6] = *(float2*)&acc[i][3];

        // classes from prefetched smem (garbage for v>=V_ is harmless: q=0 there)
        int   c[8];
#pragma unroll
        for (int h = 0; h < 2; h++) {
            int vloc = 8 * tx + 4 * h;
            int4   r4 = *(const int4*)  &rel_s [tl * 128 + vloc];
            float4 e4 = *(const float4*)&edge_s[tl * 128 + vloc];
            c[4*h+0] = (r4.x >= 1 && r4.x <= 8 && e4.x > 0.f) ? r4.x : 0;
            c[4*h+1] = (r4.y >= 1 && r4.y <= 8 && e4.y > 0.f) ? r4.y : 0;
            c[4*h+2] = (r4.z >= 1 && r4.z <= 8 && e4.z > 0.f) ? r4.z : 0;
            c[4*h+3] = (r4.w >= 1 && r4.w <= 8 && e4.w > 0.f) ? r4.w : 0;
        }
        float q[8];
#pragma unroll
        for (int k = 0; k < 8; k++) q[k] = __expf(bs[k]) - 1.f;

        *(float4*)&g_base[(size_t)t * VPAD + v0]     = make_float4(q[0], q[1], q[2], q[3]);
        *(float4*)&g_base[(size_t)t * VPAD + v0 + 4] = make_float4(q[4], q[5], q[6], q[7]);
        if (v0 < V_) {
            uint32_t pack = 0;
#pragma unroll
            for (int k = 0; k < 8; k++) pack |= ((uint32_t)c[k]) << (4 * k);
            g_cls4[(size_t)t * (VPAD/8) + (v0 >> 3)] = pack;
        }

        // per-token partial stats (17 values), reduced over 16 lanes sharing token
        float vals[17];
#pragma unroll
        for (int f = 0; f < 17; f++) vals[f] = 0.f;
#pragma unroll
        for (int k = 0; k < 8; k++) {
            float qq = q[k], bb = bs[k];
            vals[16] += bb;
            float qb = qq * bb;
#pragma unroll
            for (int r = 0; r < NR; r++) {
                if (c[k] == r + 1) { vals[r] += qq; vals[8 + r] += qb; }
            }
        }
#pragma unroll
        for (int off = 1; off < 16; off <<= 1) {
#pragma unroll
            for (int f = 0; f < 17; f++)
                vals[f] += __shfl_xor_sync(0xFFFFFFFFu, vals[f], off);
        }
        if (tx == 0) {
#pragma unroll
            for (int f = 0; f < 17; f++)
                g_sp2[((size_t)vb * 17 + f) * NTOK + t] = vals[f];
        }
    }
}

// ---------------- stats reduce: fold v-block partials, softmax weights ----------------
__global__ __launch_bounds__(256) void k_statsB() {
    int t = blockIdx.x * 256 + threadIdx.x;
    float a17[17];
#pragma unroll
    for (int f = 0; f < 17; f++) a17[f] = 0.f;
    for (int vb = 0; vb < NVB; vb++) {
#pragma unroll
        for (int f = 0; f < 17; f++)
            a17[f] += g_sp2[((size_t)vb * 17 + f) * NTOK + t];
    }
    float sc[NR], Zv[NR];
    float Bt = a17[16];
#pragma unroll
    for (int r = 0; r < NR; r++) {
        float Z = (float)V_ + a17[r];
        Zv[r] = Z;
        sc[r] = (a17[8 + r] + Bt) / Z;
    }
    float mx = sc[0];
#pragma unroll
    for (int r = 1; r < NR; r++) mx = fmaxf(mx, sc[r]);
    float es[NR], ss = 0.f;
#pragma unroll
    for (int r = 0; r < NR; r++) { es[r] = __expf(sc[r] - mx); ss += es[r]; }
    float inv = 1.f / ss;
    float beta = 0.f;
    float* st = g_stats + t * 12;
#pragma unroll
    for (int r = 0; r < NR; r++) {
        float K1 = es[r] * inv / Zv[r];
        st[r] = K1;
        beta += K1;
    }
    st[8] = beta;
}

// ---------------- final GEMM: 8 tok x 16 col per thread, 1.0 smem-B/FMA ----------------
#define KCF  16
#define NCHF (KQ / KCF)      // 40

// dynamic smem layout in floats
#define FWS_OFF  0                       // Ws[2][16][132]
#define FAS_OFF  (2 * KCF * 132)         // 4224: As2[2][16][260]
#define FK1_OFF  (FAS_OFF + 2 * KCF * 260)  // 12544: K1s[8][128]
#define FIN_SMEM ((FK1_OFF + 8 * 128) * 4)  // 54272 bytes

__global__ __launch_bounds__(128, 2) void k_final(const float* __restrict__ W) {
    extern __shared__ float smf[];
    float* WsF  = smf + FWS_OFF;   // [buf*16 + kk][132]
    float* AsF  = smf + FAS_OFF;   // [buf*16 + kk][260]
    float* K1s  = smf + FK1_OFF;   // [r][128]

    int tid = threadIdx.x;
    int t0  = blockIdx.x * 128;
    int ks  = blockIdx.y;
    int k0  = ks * KQ;

    {   // per-token K1 into transposed smem: conflict-free dynamic-class reads
        float4 k1a = *(const float4*)&g_stats[(t0 + tid) * 12];
        float4 k1b = *(const float4*)&g_stats[(t0 + tid) * 12 + 4];
        K1s[0 * 128 + tid] = k1a.x; K1s[1 * 128 + tid] = k1a.y;
        K1s[2 * 128 + tid] = k1a.z; K1s[3 * 128 + tid] = k1a.w;
        K1s[4 * 128 + tid] = k1b.x; K1s[5 * 128 + tid] = k1b.y;
        K1s[6 * 128 + tid] = k1b.z; K1s[7 * 128 + tid] = k1b.w;
    }
    __syncthreads();

    unsigned long long acc[8][8];
#pragma unroll
    for (int i = 0; i < 8; i++)
#pragma unroll
        for (int j = 0; j < 8; j++) acc[i][j] = 0ull;

    int tx = tid & 7;      // col group: 16*tx..16*tx+15
    int ty = tid >> 3;     // token group: 8*ty..8*ty+7

    float4   wst[4];
    float4   qst[4];
    uint2    cst;

    auto stage = [&](int kc) {
#pragma unroll
        for (int j = 0; j < 4; j++) {
            int p  = tid + 128 * j;
            int v  = p >> 5;
            int e4 = (p & 31) * 4;
            int gv = kc + v;
            wst[j] = (gv < V_) ? *(const float4*)&W[(size_t)gv * E_ + e4]
                               : make_float4(0.f, 0.f, 0.f, 0.f);
        }
        size_t off = (size_t)(t0 + tid) * VPAD + kc;
#pragma unroll
        for (int m = 0; m < 4; m++)
            qst[m] = *(const float4*)(g_base + off + 4 * m);
        cst = *(const uint2*)(g_cls4 + (size_t)(t0 + tid) * (VPAD/8) + (kc >> 3));
    };
    auto commit = [&](int buf) {
#pragma unroll
        for (int j = 0; j < 4; j++) {
            int p  = tid + 128 * j;
            int v  = p >> 5;
            int e4 = (p & 31) * 4;
            *(float4*)&WsF[(buf * KCF + v) * 132 + e4] = wst[j];
        }
        float qs[16];
#pragma unroll
        for (int m = 0; m < 4; m++) {
            qs[4*m+0] = qst[m].x; qs[4*m+1] = qst[m].y;
            qs[4*m+2] = qst[m].z; qs[4*m+3] = qst[m].w;
        }
#pragma unroll
        for (int j = 0; j < 16; j++) {
            uint32_t word = (j < 8) ? cst.x : cst.y;
            int cc = (word >> (4 * (j & 7))) & 15;
            float g = cc ? K1s[(cc - 1) * 128 + tid] * qs[j] : 0.f;
            *(float2*)&AsF[(buf * KCF + j) * 260 + 2 * tid] = make_float2(g, g);
        }
    };

    stage(k0);
    commit(0);
    int buf = 0;

    for (int it = 0; it < NCHF; it++) {
        __syncthreads();
        if (it + 1 < NCHF) stage(k0 + (it + 1) * KCF);
#pragma unroll
        for (int kk = 0; kk < KCF; kk++) {
            const float* wrow = &WsF[(buf * KCF + kk) * 132 + 16 * tx];
            const float* arow = &AsF[(buf * KCF + kk) * 260 + 16 * ty];
            ulonglong2 w01 = *(const ulonglong2*)(wrow);
            ulonglong2 w23 = *(const ulonglong2*)(wrow + 4);
            ulonglong2 w45 = *(const ulonglong2*)(wrow + 8);
            ulonglong2 w67 = *(const ulonglong2*)(wrow + 12);
            ulonglong2 a01 = *(const ulonglong2*)(arow);
            ulonglong2 a23 = *(const ulonglong2*)(arow + 4);
            ulonglong2 a45 = *(const ulonglong2*)(arow + 8);
            ulonglong2 a67 = *(const ulonglong2*)(arow + 12);
            unsigned long long a[8] = {a01.x, a01.y, a23.x, a23.y,
                                       a45.x, a45.y, a67.x, a67.y};
            unsigned long long w[8] = {w01.x, w01.y, w23.x, w23.y,
                                       w45.x, w45.y, w67.x, w67.y};
#pragma unroll
            for (int i = 0; i < 8; i++)
#pragma unroll
                for (int j = 0; j < 8; j++)
                    fma2(acc[i][j], a[i], w[j]);
        }
        if (it + 1 < NCHF) commit(buf ^ 1);
        buf ^= 1;
    }

    float* ps = g_psum[ks];
#pragma unroll
    for (int i = 0; i < 8; i++) {
        int t = t0 + 8 * ty + i;
#pragma unroll
        for (int m = 0; m < 4; m++) {
            float2 lo = *(float2*)&acc[i][2 * m];
            float2 hi = *(float2*)&acc[i][2 * m + 1];
            *(float4*)&ps[(size_t)t * E_ + 16 * tx + 4 * m] =
                make_float4(lo.x, lo.y, hi.x, hi.y);
        }
    }
}

// ---------------- combine K-split partials + background term ----------------
__global__ void k_combine(float* __restrict__ out) {
    int i  = blockIdx.x * 256 + threadIdx.x;
    int t  = i >> 5;
    int c4 = (i & 31) * 4;
    size_t off = (size_t)t * E_ + c4;
    float  beta = g_stats[t * 12 + 8];
    float4 cs = *(const float4*)&g_colsum[c4];
    float4 o = make_float4(beta * cs.x, beta * cs.y, beta * cs.z, beta * cs.w);
#pragma unroll
    for (int r = 0; r < KSPLIT; r++) {
        float4 a = *(const float4*)&g_psum[r][off];
        o.x += a.x; o.y += a.y; o.z += a.z; o.w += a.w;
    }
    *(float4*)&out[off] = o;
}

// ---------------- launch ----------------
extern "C" void kernel_launch(void* const* d_in, const int* in_sizes, int n_in,
                              void* d_out, int out_size) {
    const int*   src  = (const int*)  d_in[0];
    const float* X    = (const float*)d_in[1];
    const float* W    = (const float*)d_in[2];
    const float* edge = (const float*)d_in[3];
    const int*   rel  = (const int*)  d_in[4];
    float* out = (float*)d_out;

    cudaFuncSetAttribute(k_base,  cudaFuncAttributeMaxDynamicSharedMemorySize, SMEM_KB);
    cudaFuncSetAttribute(k_final, cudaFuncAttributeMaxDynamicSharedMemorySize, FIN_SMEM);

    k_colsum1<<<40, 128>>>(W);
    k_colsum2<<<1, 128>>>();

    dim3 gb(NVB, NTOK / BT);   // 79 x 32
    k_base<<<gb, 128, SMEM_KB>>>(src, X, W, edge, rel);

    k_statsB<<<NTOK / 256, 256>>>();

    k_final<<<dim3(NTOK / 128, KSPLIT), 128, FIN_SMEM>>>(W);  // 16 x 16 = 256 CTAs

    k_combine<<<256, 256>>>(out);
    (void)in_sizes; (void)n_in; (void)out_size;
}

// round 9
// speedup vs baseline: 1.7599x; 1.7599x over previous
#include <cuda_runtime.h>
#include <cstdint>

#define V_     10000
#define VPAD   10240
#define E_     128
#define NTOK   2048
#define NR     8
#define NW     1250          // class words per token (V_/8)
#define NWP    1280          // padded words per token (VPAD/8)

#define KSPLIT 16
#define KQ     640           // 16*640 = 10240 = VPAD exactly

// ---------------- scratch (device globals; no allocations) ----------------
__device__ float    g_base[(size_t)NTOK * VPAD];     // q = exp(base)-1 (pad = 0, zero-init)
__device__ uint32_t g_cls4[(size_t)NTOK * NWP];      // 4-bit classes, 8/word; pad = 0
__device__ float    g_colsum[E_];
__device__ float    g_part[40 * E_];
__device__ float    g_stats[NTOK * 12];              // K1[8], beta
__device__ float    g_psum[KSPLIT][(size_t)NTOK * E_];

__device__ __forceinline__ void fma2(unsigned long long& acc,
                                     unsigned long long a, unsigned long long b) {
    asm("fma.rn.f32x2 %0, %1, %2, %0;" : "+l"(acc) : "l"(a), "l"(b));
}

// ---------------- column sums of W (deterministic 2-stage) ----------------
__global__ void k_colsum1(const float* __restrict__ W) {
    int b = blockIdx.x, col = threadIdx.x;
    float s = 0.f;
    int v0 = b * 250;
    for (int v = v0; v < v0 + 250; v++) s += W[v * E_ + col];
    g_part[b * E_ + col] = s;
}
__global__ void k_colsum2() {
    int col = threadIdx.x;
    float s = 0.f;
    for (int b = 0; b < 40; b++) s += g_part[b * E_ + col];
    g_colsum[col] = s;
}

// ---------------- classification: rel/edge -> packed 4-bit classes ----------------
__global__ __launch_bounds__(256) void k_classify(
    const int*   __restrict__ src,
    const float* __restrict__ edge,
    const int*   __restrict__ rel)
{
    int idx = blockIdx.x * 256 + threadIdx.x;    // 2048*1250 = 2.56M words, grid=10000
    int t = idx / NW;
    int w = idx - t * NW;
    long s = src[t];
    int v0 = w * 8;
    const int*   rp = rel  + s * (long)V_ + v0;
    const float* ep = edge + s * (long)V_ + v0;
    uint32_t pack = 0;
#pragma unroll
    for (int h = 0; h < 2; h++) {
        int4   r4 = *(const int4*)  (rp + 4 * h);
        float4 e4 = *(const float4*)(ep + 4 * h);
        uint32_t cx = (r4.x >= 1 && r4.x <= 8 && e4.x > 0.f) ? (uint32_t)r4.x : 0u;
        uint32_t cy = (r4.y >= 1 && r4.y <= 8 && e4.y > 0.f) ? (uint32_t)r4.y : 0u;
        uint32_t cz = (r4.z >= 1 && r4.z <= 8 && e4.z > 0.f) ? (uint32_t)r4.z : 0u;
        uint32_t cw = (r4.w >= 1 && r4.w <= 8 && e4.w > 0.f) ? (uint32_t)r4.w : 0u;
        pack |= (cx | (cy << 4) | (cz << 8) | (cw << 12)) << (16 * h);
    }
    g_cls4[(size_t)t * NWP + w] = pack;
}

// ---------------- base GEMM (f32x2, 8x8 tile, double-buffered), writes q ----------------
#define BT 64
#define BV 128
#define KCB 16

__global__ __launch_bounds__(128, 3) void k_base(
    const float* __restrict__ X,
    const float* __restrict__ W)
{
    __shared__ float Xs2[2][KCB][132];
    __shared__ float Ws[2][KCB][132];

    int tid  = threadIdx.x;
    int vblk = blockIdx.x * BV;
    int tblk = blockIdx.y * BT;

    unsigned long long acc[8][4];
#pragma unroll
    for (int i = 0; i < 8; i++)
#pragma unroll
        for (int j = 0; j < 4; j++) acc[i][j] = 0ull;

    int tx = tid & 15;     // col group: 8*tx..8*tx+7
    int ty = tid >> 4;     // token group: 8*ty..8*ty+7
    int xtok = tid & 63, xkq = tid >> 6;
    int gvW  = vblk + tid;

    float4 xst[2], wst[4];
    auto stage = [&](int kc) {
#pragma unroll
        for (int j = 0; j < 2; j++) {
            int k4 = 4 * (xkq + 2 * j);
            xst[j] = *(const float4*)&X[(size_t)(tblk + xtok) * E_ + kc + k4];
        }
#pragma unroll
        for (int j = 0; j < 4; j++) {
            wst[j] = (gvW < V_) ? *(const float4*)&W[(size_t)gvW * E_ + kc + 4 * j]
                                : make_float4(0.f, 0.f, 0.f, 0.f);
        }
    };
    auto commit = [&](int buf) {
#pragma unroll
        for (int j = 0; j < 2; j++) {
            int k4 = 4 * (xkq + 2 * j);
            *(float2*)&Xs2[buf][k4 + 0][2 * xtok] = make_float2(xst[j].x, xst[j].x);
            *(float2*)&Xs2[buf][k4 + 1][2 * xtok] = make_float2(xst[j].y, xst[j].y);
            *(float2*)&Xs2[buf][k4 + 2][2 * xtok] = make_float2(xst[j].z, xst[j].z);
            *(float2*)&Xs2[buf][k4 + 3][2 * xtok] = make_float2(xst[j].w, xst[j].w);
        }
#pragma unroll
        for (int j = 0; j < 4; j++) {
            int k4 = 4 * j;
            Ws[buf][k4 + 0][tid] = wst[j].x;
            Ws[buf][k4 + 1][tid] = wst[j].y;
            Ws[buf][k4 + 2][tid] = wst[j].z;
            Ws[buf][k4 + 3][tid] = wst[j].w;
        }
    };

    stage(0);
    commit(0);
    int buf = 0;
#define NCHB (E_ / KCB)   // 8
    for (int ch = 0; ch < NCHB; ch++) {
        __syncthreads();
        if (ch + 1 < NCHB) stage((ch + 1) * KCB);
#pragma unroll
        for (int kk = 0; kk < KCB; kk++) {
            ulonglong2 w01 = *(const ulonglong2*)&Ws[buf][kk][8 * tx];
            ulonglong2 w23 = *(const ulonglong2*)&Ws[buf][kk][8 * tx + 4];
            ulonglong2 a01 = *(const ulonglong2*)&Xs2[buf][kk][16 * ty];
            ulonglong2 a23 = *(const ulonglong2*)&Xs2[buf][kk][16 * ty + 4];
            ulonglong2 a45 = *(const ulonglong2*)&Xs2[buf][kk][16 * ty + 8];
            ulonglong2 a67 = *(const ulonglong2*)&Xs2[buf][kk][16 * ty + 12];
            unsigned long long a[8] = {a01.x, a01.y, a23.x, a23.y,
                                       a45.x, a45.y, a67.x, a67.y};
            unsigned long long w[4] = {w01.x, w01.y, w23.x, w23.y};
#pragma unroll
            for (int i = 0; i < 8; i++)
#pragma unroll
                for (int j = 0; j < 4; j++)
                    fma2(acc[i][j], a[i], w[j]);
        }
        if (ch + 1 < NCHB) commit(buf ^ 1);
        buf ^= 1;
    }

    int v0 = vblk + 8 * tx;
#pragma unroll
    for (int i = 0; i < 8; i++) {
        int t  = tblk + 8 * ty + i;
        float2 p0 = *(float2*)&acc[i][0];
        float2 p1 = *(float2*)&acc[i][1];
        float2 p2 = *(float2*)&acc[i][2];
        float2 p3 = *(float2*)&acc[i][3];
        float4 q0 = make_float4(__expf(p0.x) - 1.f, __expf(p0.y) - 1.f,
                                __expf(p1.x) - 1.f, __expf(p1.y) - 1.f);
        float4 q1 = make_float4(__expf(p2.x) - 1.f, __expf(p2.y) - 1.f,
                                __expf(p3.x) - 1.f, __expf(p3.y) - 1.f);
        *(float4*)&g_base[(size_t)t * VPAD + v0]     = q0;
        *(float4*)&g_base[(size_t)t * VPAD + v0 + 4] = q1;
    }
}

// ---------------- per-(t,r) stats: 2-copy lane-private smem RMW ----------------
#define CSTRIDE 33

__global__ __launch_bounds__(256) void k_stats() {
    __shared__ float2 accs[2][8][9 * CSTRIDE];   // [copy][warp][class*33 + lane]
    __shared__ float  eArr[NR], dArr[NR], Bsh[8];

    int t   = blockIdx.x;
    int tid = threadIdx.x;
    int w   = tid >> 5, lane = tid & 31;

    for (int i = tid; i < 2 * 8 * 9 * CSTRIDE; i += 256)
        ((float2*)accs)[i] = make_float2(0.f, 0.f);
    __syncthreads();

    float B = 0.f;
    const float*    qRow = g_base + (size_t)t * VPAD;
    const uint32_t* cRow = g_cls4 + (size_t)t * NWP;

    for (int i = tid; i < NW; i += 256) {
        float4 qa = *(const float4*)(qRow + 8 * i);
        float4 qb = *(const float4*)(qRow + 8 * i + 4);
        uint32_t cw = cRow[i];
        float qs[8] = {qa.x, qa.y, qa.z, qa.w, qb.x, qb.y, qb.z, qb.w};
#pragma unroll
        for (int j = 0; j < 8; j++) {
            float q = qs[j];
            int   c = (cw >> (4 * j)) & 15;
            float b = __logf(fmaxf(q + 1.f, 1e-38f));
            B += b;
            float2* p = &accs[j & 1][w][c * CSTRIDE + lane];
            float2 o = *p;
            o.x += q;
            o.y = fmaf(q, b, o.y);
            *p = o;
        }
    }
#pragma unroll
    for (int o = 16; o; o >>= 1) B += __shfl_xor_sync(0xFFFFFFFFu, B, o);
    if (lane == 0) Bsh[w] = B;
    __syncthreads();

    // class reduce: warp w handles class w+1, both copies
    {
        float2 s = make_float2(0.f, 0.f);
#pragma unroll
        for (int ww = 0; ww < 8; ww++) {
            float2 a0 = accs[0][ww][(w + 1) * CSTRIDE + lane];
            float2 a1 = accs[1][ww][(w + 1) * CSTRIDE + lane];
            s.x += a0.x + a1.x;
            s.y += a0.y + a1.y;
        }
#pragma unroll
        for (int o = 16; o; o >>= 1) {
            s.x += __shfl_xor_sync(0xFFFFFFFFu, s.x, o);
            s.y += __shfl_xor_sync(0xFFFFFFFFu, s.y, o);
        }
        if (lane == 0) { eArr[w] = s.x; dArr[w] = s.y; }
    }
    __syncthreads();

    if (tid == 0) {
        float Bt = 0.f;
#pragma unroll
        for (int k = 0; k < 8; k++) Bt += Bsh[k];
        float sc[NR], Zv[NR];
#pragma unroll
        for (int r = 0; r < NR; r++) {
            float Z = (float)V_ + eArr[r];
            Zv[r] = Z;
            sc[r] = (dArr[r] + Bt) / Z;
        }
        float mx = sc[0];
#pragma unroll
        for (int r = 1; r < NR; r++) mx = fmaxf(mx, sc[r]);
        float es[NR], ss = 0.f;
#pragma unroll
        for (int r = 0; r < NR; r++) { es[r] = __expf(sc[r] - mx); ss += es[r]; }
        float inv = 1.f / ss;
        float beta = 0.f;
        float* st = g_stats + t * 12;
#pragma unroll
        for (int r = 0; r < NR; r++) {
            float K1 = es[r] * inv / Zv[r];
            st[r] = K1;
            beta += K1;
        }
        st[8] = beta;
    }
}

// ---------------- final GEMM: 8 tok x 16 col per thread (FMA-bound tile) ----------------
#define KCF  16
#define NCHF (KQ / KCF)      // 40

// dynamic smem layout in floats
#define FWS_OFF  0                          // Ws[2][16][132]
#define FAS_OFF  (2 * KCF * 132)            // As2[2][16][260]
#define FK1_OFF  (FAS_OFF + 2 * KCF * 260)  // K1s[8][128]
#define FIN_SMEM ((FK1_OFF + 8 * 128) * 4)  // 54272 bytes

__global__ __launch_bounds__(128, 2) void k_final(const float* __restrict__ W) {
    extern __shared__ float smf[];
    float* WsF  = smf + FWS_OFF;
    float* AsF  = smf + FAS_OFF;
    float* K1s  = smf + FK1_OFF;

    int tid = threadIdx.x;
    int t0  = blockIdx.x * 128;
    int ks  = blockIdx.y;
    int k0  = ks * KQ;

    {   // per-token K1 transposed: conflict-free dynamic-class reads
        float4 k1a = *(const float4*)&g_stats[(t0 + tid) * 12];
        float4 k1b = *(const float4*)&g_stats[(t0 + tid) * 12 + 4];
        K1s[0 * 128 + tid] = k1a.x; K1s[1 * 128 + tid] = k1a.y;
        K1s[2 * 128 + tid] = k1a.z; K1s[3 * 128 + tid] = k1a.w;
        K1s[4 * 128 + tid] = k1b.x; K1s[5 * 128 + tid] = k1b.y;
        K1s[6 * 128 + tid] = k1b.z; K1s[7 * 128 + tid] = k1b.w;
    }
    __syncthreads();

    unsigned long long acc[8][8];
#pragma unroll
    for (int i = 0; i < 8; i++)
#pragma unroll
        for (int j = 0; j < 8; j++) acc[i][j] = 0ull;

    int tx = tid & 7;      // col group: 16*tx..16*tx+15
    int ty = tid >> 3;     // token group: 8*ty..8*ty+7

    float4   wst[4];
    float4   qst[4];
    uint2    cst;

    auto stage = [&](int kc) {
#pragma unroll
        for (int j = 0; j < 4; j++) {
            int p  = tid + 128 * j;
            int v  = p >> 5;
            int e4 = (p & 31) * 4;
            int gv = kc + v;
            wst[j] = (gv < V_) ? *(const float4*)&W[(size_t)gv * E_ + e4]
                               : make_float4(0.f, 0.f, 0.f, 0.f);
        }
        size_t off = (size_t)(t0 + tid) * VPAD + kc;
#pragma unroll
        for (int m = 0; m < 4; m++)
            qst[m] = *(const float4*)(g_base + off + 4 * m);
        cst = *(const uint2*)(g_cls4 + (size_t)(t0 + tid) * NWP + (kc >> 3));
    };
    auto commit = [&](int buf) {
#pragma unroll
        for (int j = 0; j < 4; j++) {
            int p  = tid + 128 * j;
            int v  = p >> 5;
            int e4 = (p & 31) * 4;
            *(float4*)&WsF[(buf * KCF + v) * 132 + e4] = wst[j];
        }
        float qs[16];
#pragma unroll
        for (int m = 0; m < 4; m++) {
            qs[4*m+0] = qst[m].x; qs[4*m+1] = qst[m].y;
            qs[4*m+2] = qst[m].z; qs[4*m+3] = qst[m].w;
        }
#pragma unroll
        for (int j = 0; j < 16; j++) {
            uint32_t word = (j < 8) ? cst.x : cst.y;
            int cc = (word >> (4 * (j & 7))) & 15;
            float g = cc ? K1s[(cc - 1) * 128 + tid] * qs[j] : 0.f;
            *(float2*)&AsF[(buf * KCF + j) * 260 + 2 * tid] = make_float2(g, g);
        }
    };

    stage(k0);
    commit(0);
    int buf = 0;

    for (int it = 0; it < NCHF; it++) {
        __syncthreads();
        if (it + 1 < NCHF) stage(k0 + (it + 1) * KCF);
#pragma unroll
        for (int kk = 0; kk < KCF; kk++) {
            const float* wrow = &WsF[(buf * KCF + kk) * 132 + 16 * tx];
            const float* arow = &AsF[(buf * KCF + kk) * 260 + 16 * ty];
            ulonglong2 w01 = *(const ulonglong2*)(wrow);
            ulonglong2 w23 = *(const ulonglong2*)(wrow + 4);
            ulonglong2 w45 = *(const ulonglong2*)(wrow + 8);
            ulonglong2 w67 = *(const ulonglong2*)(wrow + 12);
            ulonglong2 a01 = *(const ulonglong2*)(arow);
            ulonglong2 a23 = *(const ulonglong2*)(arow + 4);
            ulonglong2 a45 = *(const ulonglong2*)(arow + 8);
            ulonglong2 a67 = *(const ulonglong2*)(arow + 12);
            unsigned long long a[8] = {a01.x, a01.y, a23.x, a23.y,
                                       a45.x, a45.y, a67.x, a67.y};
            unsigned long long w[8] = {w01.x, w01.y, w23.x, w23.y,
                                       w45.x, w45.y, w67.x, w67.y};
#pragma unroll
            for (int i = 0; i < 8; i++)
#pragma unroll
                for (int j = 0; j < 8; j++)
                    fma2(acc[i][j], a[i], w[j]);
        }
        if (it + 1 < NCHF) commit(buf ^ 1);
        buf ^= 1;
    }

    float* ps = g_psum[ks];
#pragma unroll
    for (int i = 0; i < 8; i++) {
        int t = t0 + 8 * ty + i;
#pragma unroll
        for (int m = 0; m < 4; m++) {
            float2 lo = *(float2*)&acc[i][2 * m];
            float2 hi = *(float2*)&acc[i][2 * m + 1];
            *(float4*)&ps[(size_t)t * E_ + 16 * tx + 4 * m] =
                make_float4(lo.x, lo.y, hi.x, hi.y);
        }
    }
}

// ---------------- combine K-split partials + background term ----------------
__global__ void k_combine(float* __restrict__ out) {
    int i  = blockIdx.x * 256 + threadIdx.x;
    int t  = i >> 5;
    int c4 = (i & 31) * 4;
    size_t off = (size_t)t * E_ + c4;
    float  beta = g_stats[t * 12 + 8];
    float4 cs = *(const float4*)&g_colsum[c4];
    float4 o = make_float4(beta * cs.x, beta * cs.y, beta * cs.z, beta * cs.w);
#pragma unroll
    for (int r = 0; r < KSPLIT; r++) {
        float4 a = *(const float4*)&g_psum[r][off];
        o.x += a.x; o.y += a.y; o.z += a.z; o.w += a.w;
    }
    *(float4*)&out[off] = o;
}

// ---------------- launch ----------------
extern "C" void kernel_launch(void* const* d_in, const int* in_sizes, int n_in,
                              void* d_out, int out_size) {
    const int*   src  = (const int*)  d_in[0];
    const float* X    = (const float*)d_in[1];
    const float* W    = (const float*)d_in[2];
    const float* edge = (const float*)d_in[3];
    const int*   rel  = (const int*)  d_in[4];
    float* out = (float*)d_out;

    cudaFuncSetAttribute(k_final, cudaFuncAttributeMaxDynamicSharedMemorySize, FIN_SMEM);

    k_colsum1<<<40, 128>>>(W);
    k_colsum2<<<1, 128>>>();

    k_classify<<<(NTOK * NW) / 256, 256>>>(src, edge, rel);   // 10000 CTAs

    dim3 gb((V_ + BV - 1) / BV, NTOK / BT);   // 79 x 32
    k_base<<<gb, 128>>>(X, W);

    k_stats<<<NTOK, 256>>>();

    k_final<<<dim3(NTOK / 128, KSPLIT), 128, FIN_SMEM>>>(W);  // 16 x 16 = 256 CTAs

    k_combine<<<256, 256>>>(out);
    (void)in_sizes; (void)n_in; (void)out_size;
}